// round 15
// baseline (speedup 1.0000x reference)
#include <cuda_runtime.h>
#include <cuda_fp16.h>
#include <math.h>

#define N_NODES 20000
#define N_EDGES 80000
#define DIM 64
#define EDIM 12
#define BCOLS 1408   // tf32 B: cols 1024..1215 wih^T, 1216..1407 whh^T
#define BN_EPS 1e-5f
#define BN_BLOCKS 296
#define NCHUNK 13    // 12 lin_w k-blocks + 1 bias block

// ---------------- scratch ----------------
__device__ __half g_LWt[NCHUNK * 64 * 64];       // [kc][o][i] fp16 (bias chunk at kc=12)
__device__ float g_B[64 * BCOLS];
__device__ float g_GI[(size_t)N_NODES * 192];    // relu(agg)/cnt @ w_ih^T
__device__ float g_GH[(size_t)N_NODES * 192];    // x @ w_hh^T
__device__ float g_agg[(size_t)N_NODES * DIM];
__device__ float g_cnt[N_NODES];
__device__ float g_bnpart[BN_BLOCKS * 2 * EDIM];
__device__ float g_scale[EDIM];
__device__ float g_shift[EDIM];

__device__ __forceinline__ float f2tf32(float f) {
    unsigned u;
    asm("cvt.rna.tf32.f32 %0, %1;" : "=r"(u) : "f"(f));
    return __uint_as_float(u);
}

// ---------------- kernel 1: pack weights + zero agg/cnt + BN partial sums ----------------
__global__ void k_prologue(const float* __restrict__ lw, const float* __restrict__ lb,
                           const float* __restrict__ whh, const float* __restrict__ wih,
                           const float* __restrict__ ea) {
    int idx = blockIdx.x * blockDim.x + threadIdx.x;
    int stride = gridDim.x * blockDim.x;

    float4* aggz = (float4*)g_agg;
    for (int j = idx; j < N_NODES * DIM / 4; j += stride)
        aggz[j] = make_float4(0.f, 0.f, 0.f, 0.f);
    for (int j = idx; j < N_NODES; j += stride) g_cnt[j] = 0.f;

    // LWt[kc][o][i]: transpose of lin_w k-blocks; chunk 12 = lin_b
    for (int t = idx; t < NCHUNK * 4096; t += stride) {
        int kc = t >> 12, rem = t & 4095;
        int o = rem >> 6, i = rem & 63;
        float v = (kc < 12) ? lw[(size_t)kc * 4096 + i * 64 + o] : lb[i * 64 + o];
        g_LWt[t] = __float2half_rn(v);
    }
    // tf32 packs for GI / GH gemms
    for (int t = idx; t < 64 * 192; t += stride) {
        int i = t / 192, g = t % 192;
        g_B[(size_t)i * BCOLS + 1024 + g] = f2tf32(wih[g * 64 + i]);
        g_B[(size_t)i * BCOLS + 1216 + g] = f2tf32(whh[g * 64 + i]);
    }

    // BN column partial sums
    float s[EDIM], q[EDIM];
#pragma unroll
    for (int c = 0; c < EDIM; c++) { s[c] = 0.f; q[c] = 0.f; }
    for (int e = idx; e < N_EDGES; e += stride) {
        const float* row = ea + (size_t)e * EDIM;
#pragma unroll
        for (int c = 0; c < EDIM; c++) { float v = row[c]; s[c] += v; q[c] += v * v; }
    }
#pragma unroll
    for (int off = 16; off > 0; off >>= 1) {
#pragma unroll
        for (int c = 0; c < EDIM; c++) {
            s[c] += __shfl_down_sync(0xffffffffu, s[c], off);
            q[c] += __shfl_down_sync(0xffffffffu, q[c], off);
        }
    }
    __shared__ float bs[2 * EDIM];
    if (threadIdx.x < 2 * EDIM) bs[threadIdx.x] = 0.f;
    __syncthreads();
    if ((threadIdx.x & 31) == 0) {
#pragma unroll
        for (int c = 0; c < EDIM; c++) {
            atomicAdd(&bs[c], s[c]);
            atomicAdd(&bs[EDIM + c], q[c]);
        }
    }
    __syncthreads();
    if (threadIdx.x < 2 * EDIM)
        g_bnpart[blockIdx.x * 2 * EDIM + threadIdx.x] = bs[threadIdx.x];
}

// ---------------- kernel 2: BN finalize ----------------
__global__ void k_bn_fin(const float* __restrict__ gamma, const float* __restrict__ beta) {
    int t = threadIdx.x;
    __shared__ float red[2 * EDIM];
    if (t < 2 * EDIM) {
        float acc = 0.f;
        for (int b = 0; b < BN_BLOCKS; b++) acc += g_bnpart[b * 2 * EDIM + t];
        red[t] = acc;
    }
    __syncwarp();
    if (t < EDIM) {
        float inv_n = 1.0f / (float)N_EDGES;
        float mu = red[t] * inv_n;
        float var = red[EDIM + t] * inv_n - mu * mu;
        float sc = rsqrtf(var + BN_EPS) * gamma[t];
        g_scale[t] = sc;
        g_shift[t] = beta[t] - mu * sc;
    }
}

// ---------------- fp16 mma helpers ----------------
__device__ __forceinline__ void mma_f16(float* c, const unsigned* a, unsigned b0, unsigned b1) {
    asm volatile(
        "mma.sync.aligned.m16n8k16.row.col.f32.f16.f16.f32 "
        "{%0,%1,%2,%3}, {%4,%5,%6,%7}, {%8,%9}, {%0,%1,%2,%3};"
        : "+f"(c[0]), "+f"(c[1]), "+f"(c[2]), "+f"(c[3])
        : "r"(a[0]), "r"(a[1]), "r"(a[2]), "r"(a[3]), "r"(b0), "r"(b1));
}

__device__ __forceinline__ void ldsm_x4(unsigned* r, unsigned addr) {
    asm volatile("ldmatrix.sync.aligned.m8n8.x4.shared.b16 {%0,%1,%2,%3}, [%4];"
                 : "=r"(r[0]), "=r"(r[1]), "=r"(r[2]), "=r"(r[3]) : "r"(addr));
}

// ---------------- kernel 3: fused edge message GEMM + scatter ----------------
// Block = 128 edges. msg[r] = sum_kc c[r,kc] * (x[src_r] @ LWt[kc])  (c[12] == 1 for bias).
// The per-row scale commutes into the A fragments (fp16 HMUL2); fp32 MMA accumulation.
__global__ void __launch_bounds__(256, 2) k_edge_fused(const float* __restrict__ ea,
                                                       const int* __restrict__ ei,
                                                       const float* __restrict__ x) {
    __shared__ __align__(16) __half Xs[128 * 64];     // gathered x rows, swizzled
    __shared__ __align__(16) __half Wb[2][64 * 64];   // double-buffered weight chunks
    __shared__ __half ebn_s[NCHUNK][128];
    __shared__ int srcs[128], dsts[128];

    int tid = threadIdx.x;
    int wid = tid >> 5, lane = tid & 31;
    int e0 = blockIdx.x * 128;

    if (tid < 128) {
        srcs[tid] = ei[e0 + tid];
        dsts[tid] = ei[N_EDGES + e0 + tid];
    }
    __syncthreads();

    // gather x rows (fp16, swizzled): 1024 16B slots
#pragma unroll
    for (int r = 0; r < 4; r++) {
        int s = r * 256 + tid;
        int row = s >> 3, c = s & 7;
        const float* px = &x[(size_t)srcs[row] * 64 + c * 8];
        float4 v0 = *(const float4*)px;
        float4 v1 = *(const float4*)(px + 4);
        half2 h[4] = {__floats2half2_rn(v0.x, v0.y), __floats2half2_rn(v0.z, v0.w),
                      __floats2half2_rn(v1.x, v1.y), __floats2half2_rn(v1.z, v1.w)};
        *(uint4*)&Xs[row * 64 + ((c ^ (row & 7)) << 3)] = *(uint4*)h;
    }
    // ebn coefficients (fp16), chunk 12 = 1.0 (bias)
    for (int j = tid; j < NCHUNK * 128; j += 256) {
        int kc = j >> 7, rr = j & 127;
        float v = 1.0f;
        if (kc < 12) v = ea[(size_t)(e0 + rr) * EDIM + kc] * g_scale[kc] + g_shift[kc];
        ebn_s[kc][rr] = __float2half_rn(v);
    }
    // prefetch weight chunk 0: 512 16B slots
#pragma unroll
    for (int r = 0; r < 2; r++) {
        int s = r * 256 + tid;
        int row = s >> 3, c = s & 7;
        uint4 v = *(const uint4*)&g_LWt[row * 64 + c * 8];
        *(uint4*)&Wb[0][row * 64 + ((c ^ (row & 7)) << 3)] = v;
    }
    __syncthreads();

    int warp_m = wid & 3;     // 32 edge-rows
    int warp_n = wid >> 2;    // 32 out-cols
    int lrow = lane & 15;
    int lsel = lane >> 4;
    int gid = lane >> 2;
    int tig = lane & 3;

    unsigned xs_base = (unsigned)__cvta_generic_to_shared(Xs);
    unsigned wb_base0 = (unsigned)__cvta_generic_to_shared(Wb[0]);
    unsigned wb_base1 = (unsigned)__cvta_generic_to_shared(Wb[1]);

    // preload A fragments for all 4 k16-steps (reused across all 13 chunks)
    unsigned a_all[4][2][4];
#pragma unroll
    for (int ks = 0; ks < 4; ks++) {
        int chunk = ks * 2 + lsel;
#pragma unroll
        for (int mt = 0; mt < 2; mt++) {
            int row = warp_m * 32 + mt * 16 + lrow;
            ldsm_x4(a_all[ks][mt], xs_base + (row * 64 + ((chunk ^ (row & 7)) << 3)) * 2);
        }
    }

    float msg[2][4][4];
#pragma unroll
    for (int mt = 0; mt < 2; mt++)
#pragma unroll
        for (int nt = 0; nt < 4; nt++)
#pragma unroll
            for (int j = 0; j < 4; j++) msg[mt][nt][j] = 0.f;

#pragma unroll 1
    for (int kc = 0; kc < NCHUNK; kc++) {
        int cur = kc & 1;
        // prefetch next chunk into the other buffer
        if (kc < NCHUNK - 1) {
#pragma unroll
            for (int r = 0; r < 2; r++) {
                int s = r * 256 + tid;
                int row = s >> 3, c = s & 7;
                uint4 v = *(const uint4*)&g_LWt[(size_t)(kc + 1) * 4096 + row * 64 + c * 8];
                *(uint4*)&Wb[cur ^ 1][row * 64 + ((c ^ (row & 7)) << 3)] = v;
            }
        }
        unsigned wb_base = cur ? wb_base1 : wb_base0;

        __half2 cl[2], ch[2];
#pragma unroll
        for (int mt = 0; mt < 2; mt++) {
            cl[mt] = __half2half2(ebn_s[kc][warp_m * 32 + mt * 16 + gid]);
            ch[mt] = __half2half2(ebn_s[kc][warp_m * 32 + mt * 16 + gid + 8]);
        }

#pragma unroll
        for (int ks = 0; ks < 4; ks++) {
            int chunk = ks * 2 + lsel;
            unsigned as[2][4];
#pragma unroll
            for (int mt = 0; mt < 2; mt++) {
                // a0,a2 -> row gid ; a1,a3 -> row gid+8 (std m16n8k16 A layout)
                __half2 t0 = __hmul2(*(__half2*)&a_all[ks][mt][0], cl[mt]);
                __half2 t1 = __hmul2(*(__half2*)&a_all[ks][mt][1], ch[mt]);
                __half2 t2 = __hmul2(*(__half2*)&a_all[ks][mt][2], cl[mt]);
                __half2 t3 = __hmul2(*(__half2*)&a_all[ks][mt][3], ch[mt]);
                as[mt][0] = *(unsigned*)&t0;
                as[mt][1] = *(unsigned*)&t1;
                as[mt][2] = *(unsigned*)&t2;
                as[mt][3] = *(unsigned*)&t3;
            }
#pragma unroll
            for (int nt2 = 0; nt2 < 2; nt2++) {
                int row = warp_n * 32 + nt2 * 16 + lrow;
                unsigned b[4];
                ldsm_x4(b, wb_base + (row * 64 + ((chunk ^ (row & 7)) << 3)) * 2);
                mma_f16(msg[0][nt2 * 2],     as[0], b[0], b[2]);
                mma_f16(msg[0][nt2 * 2 + 1], as[0], b[1], b[3]);
                mma_f16(msg[1][nt2 * 2],     as[1], b[0], b[2]);
                mma_f16(msg[1][nt2 * 2 + 1], as[1], b[1], b[3]);
            }
        }
        __syncthreads();
    }

    // scatter: atomic add into agg[dst]
#pragma unroll
    for (int mt = 0; mt < 2; mt++) {
        int r0 = warp_m * 32 + mt * 16 + gid;
        int d0 = dsts[r0], d1 = dsts[r0 + 8];
#pragma unroll
        for (int nt = 0; nt < 4; nt++) {
            int cb = warp_n * 32 + nt * 8 + tig * 2;
            atomicAdd(&g_agg[(size_t)d0 * 64 + cb],     msg[mt][nt][0]);
            atomicAdd(&g_agg[(size_t)d0 * 64 + cb + 1], msg[mt][nt][1]);
            atomicAdd(&g_agg[(size_t)d1 * 64 + cb],     msg[mt][nt][2]);
            atomicAdd(&g_agg[(size_t)d1 * 64 + cb + 1], msg[mt][nt][3]);
        }
    }
    if (tid < 128) atomicAdd(&g_cnt[dsts[tid]], 1.0f);
}

// ---------------- mma tf32 ----------------
__device__ __forceinline__ void mma_tf32(float* c, const unsigned* a, unsigned b0, unsigned b1) {
    asm volatile(
        "mma.sync.aligned.m16n8k8.row.col.f32.tf32.tf32.f32 "
        "{%0,%1,%2,%3}, {%4,%5,%6,%7}, {%8,%9}, {%0,%1,%2,%3};"
        : "+f"(c[0]), "+f"(c[1]), "+f"(c[2]), "+f"(c[3])
        : "r"(a[0]), "r"(a[1]), "r"(a[2]), "r"(a[3]), "r"(b0), "r"(b1));
}

#define GA_PITCH 68
#define GB_PITCH 132
#define G2_SMEM ((128 * GA_PITCH + 64 * GB_PITCH) * 4)

// shared tf32 GEMM body: C[128 x 192] tile = A[128 x 64] @ B(cols)[64 x 192]
__device__ __forceinline__ void gemm_192_body(const float* Bg, float* Cg, bool do_mrelu,
                                              const float* __restrict__ xin) {
    extern __shared__ char smraw[];
    float* As = (float*)smraw;
    float* Bs = (float*)smraw + 128 * GA_PITCH;
    const int Ncols = 192;

    int tid = threadIdx.x;
    int m0 = blockIdx.x * 128;
    int n0 = blockIdx.y * 128;

#pragma unroll
    for (int r = 0; r < 8; r++) {
        int id = r * 256 + tid;
        int m = id >> 4;
        int k4 = (id & 15) << 2;
        float4 v = make_float4(0.f, 0.f, 0.f, 0.f);
        int node = m0 + m;
        if (node < N_NODES) {
            if (do_mrelu) {
                float inv = 1.0f / fmaxf(g_cnt[node], 1.0f);
                float4 a = *(const float4*)&g_agg[(size_t)node * 64 + k4];
                v.x = fmaxf(a.x, 0.f) * inv;
                v.y = fmaxf(a.y, 0.f) * inv;
                v.z = fmaxf(a.z, 0.f) * inv;
                v.w = fmaxf(a.w, 0.f) * inv;
            } else {
                v = *(const float4*)&xin[(size_t)node * 64 + k4];
            }
        }
        v.x = f2tf32(v.x); v.y = f2tf32(v.y); v.z = f2tf32(v.z); v.w = f2tf32(v.w);
        *(float4*)&As[m * GA_PITCH + k4] = v;
    }
#pragma unroll
    for (int r = 0; r < 8; r++) {
        int id = r * 256 + tid;
        int k = id >> 5;
        int n4 = (id & 31) << 2;
        float4 v = make_float4(0.f, 0.f, 0.f, 0.f);
        if (n0 + n4 < Ncols) v = *(const float4*)&Bg[(size_t)k * BCOLS + n0 + n4];
        *(float4*)&Bs[k * GB_PITCH + n4] = v;
    }
    __syncthreads();

    int wid = tid >> 5;
    int lane = tid & 31;
    int gid = lane >> 2;
    int tig = lane & 3;
    int warp_m = wid & 3;
    int warp_n = wid >> 2;

    float acc[2][8][4];
#pragma unroll
    for (int mt = 0; mt < 2; mt++)
#pragma unroll
        for (int nt = 0; nt < 8; nt++)
#pragma unroll
            for (int j = 0; j < 4; j++) acc[mt][nt][j] = 0.f;

#pragma unroll
    for (int ks = 0; ks < 8; ks++) {
        int k0 = ks * 8;
        unsigned a[2][4];
#pragma unroll
        for (int mt = 0; mt < 2; mt++) {
            int rowb = warp_m * 32 + mt * 16;
            a[mt][0] = __float_as_uint(As[(rowb + gid) * GA_PITCH + k0 + tig]);
            a[mt][1] = __float_as_uint(As[(rowb + gid + 8) * GA_PITCH + k0 + tig]);
            a[mt][2] = __float_as_uint(As[(rowb + gid) * GA_PITCH + k0 + tig + 4]);
            a[mt][3] = __float_as_uint(As[(rowb + gid + 8) * GA_PITCH + k0 + tig + 4]);
        }
#pragma unroll
        for (int nt = 0; nt < 8; nt++) {
            int nb = warp_n * 64 + nt * 8 + gid;
            unsigned b0 = __float_as_uint(Bs[(k0 + tig) * GB_PITCH + nb]);
            unsigned b1 = __float_as_uint(Bs[(k0 + tig + 4) * GB_PITCH + nb]);
            mma_tf32(acc[0][nt], a[0], b0, b1);
            mma_tf32(acc[1][nt], a[1], b0, b1);
        }
    }

#pragma unroll
    for (int mt = 0; mt < 2; mt++) {
#pragma unroll
        for (int nt = 0; nt < 8; nt++) {
            int col = n0 + warp_n * 64 + nt * 8 + tig * 2;
            if (col >= Ncols) continue;
            int r0 = m0 + warp_m * 32 + mt * 16 + gid;
            if (r0 < N_NODES)
                *(float2*)&Cg[(size_t)r0 * 192 + col] = make_float2(acc[mt][nt][0], acc[mt][nt][1]);
            int r1 = r0 + 8;
            if (r1 < N_NODES)
                *(float2*)&Cg[(size_t)r1 * 192 + col] = make_float2(acc[mt][nt][2], acc[mt][nt][3]);
        }
    }
}

// kernel 4: GH = x @ w_hh^T   (independent of edges)
__global__ void k_gh(const float* __restrict__ x) {
    gemm_192_body(g_B + 1216, g_GH, false, x);
}
// kernel 5: GI = relu(agg)/cnt @ w_ih^T
__global__ void k_gemm2() {
    gemm_192_body(g_B + 1024, g_GI, true, (const float*)0);
}

// ---------------- kernel 6: elementwise GRU ----------------
__global__ void k_out(const float* __restrict__ x,
                      const float* __restrict__ bih, const float* __restrict__ bhh,
                      float* __restrict__ out) {
    int idx = blockIdx.x * blockDim.x + threadIdx.x;
    if (idx >= N_NODES * DIM) return;
    int n = idx >> 6;
    int o = idx & 63;

    const float* gi = g_GI + (size_t)n * 192;
    const float* gh = g_GH + (size_t)n * 192;

    float ir = gi[o] + bih[o];
    float iz = gi[64 + o] + bih[64 + o];
    float in_ = gi[128 + o] + bih[128 + o];
    float hr = gh[o] + bhh[o];
    float hz = gh[64 + o] + bhh[64 + o];
    float hn = gh[128 + o] + bhh[128 + o];

    float r = 1.0f / (1.0f + __expf(-(ir + hr)));
    float z = 1.0f / (1.0f + __expf(-(iz + hz)));
    float nn = tanhf(in_ + r * hn);
    float xv = x[idx];
    out[idx] = (1.0f - z) * nn + z * xv;
}

// ---------------- host ----------------
extern "C" void kernel_launch(void* const* d_in, const int* in_sizes, int n_in,
                              void* d_out, int out_size) {
    const float* x     = (const float*)d_in[0];
    const int*   ei    = (const int*)d_in[1];
    const float* ea    = (const float*)d_in[2];
    const float* gamma = (const float*)d_in[3];
    const float* beta  = (const float*)d_in[4];
    const float* lw    = (const float*)d_in[5];
    const float* lb    = (const float*)d_in[6];
    const float* wih   = (const float*)d_in[7];
    const float* whh   = (const float*)d_in[8];
    const float* bih   = (const float*)d_in[9];
    const float* bhh   = (const float*)d_in[10];
    float* out = (float*)d_out;

    cudaFuncSetAttribute(k_gh, cudaFuncAttributeMaxDynamicSharedMemorySize, G2_SMEM);
    cudaFuncSetAttribute(k_gemm2, cudaFuncAttributeMaxDynamicSharedMemorySize, G2_SMEM);

    k_prologue<<<BN_BLOCKS, 256>>>(lw, lb, whh, wih, ea);
    k_bn_fin<<<1, 32>>>(gamma, beta);

    dim3 gg((N_NODES + 127) / 128, 2);
    k_gh<<<gg, 256, G2_SMEM>>>(x);

    k_edge_fused<<<N_EDGES / 128, 256>>>(ea, ei, x);

    k_gemm2<<<gg, 256, G2_SMEM>>>();

    k_out<<<(N_NODES * DIM + 255) / 256, 256>>>(x, bih, bhh, out);
}

// round 17
// speedup vs baseline: 1.2697x; 1.2697x over previous
#include <cuda_runtime.h>
#include <cuda_fp16.h>
#include <math.h>

#define N_NODES 20000
#define N_EDGES 80000
#define DIM 64
#define EDIM 12
#define PCOLS 1024   // 12*64 W blocks + 64 bias block + 192 gh (x @ w_hh^T)
#define BCOLS 1216
#define BN_EPS 1e-5f
#define BN_BLOCKS 296

// ---------------- scratch ----------------
__device__ __half g_Ph[(size_t)N_NODES * PCOLS]; // 41 MB fp16 P
__device__ __half g_Bh[1024 * 64];               // B^T fp16: [j][k] for gemm1
__device__ float g_B[64 * BCOLS];                // tf32 B (cols 1024..1215 used by gemm2)
__device__ float g_GI[(size_t)N_NODES * 192];    // m @ w_ih^T
__device__ float g_agg[(size_t)N_NODES * DIM];
__device__ float g_cnt[N_NODES];
__device__ float g_bnpart[BN_BLOCKS * 2 * EDIM];
__device__ float g_scale[EDIM];
__device__ float g_shift[EDIM];

__device__ __forceinline__ float f2tf32(float f) {
    unsigned u;
    asm("cvt.rna.tf32.f32 %0, %1;" : "=r"(u) : "f"(f));
    return __uint_as_float(u);
}

// ---------------- kernel 1: pack weights + zero agg/cnt + BN partial sums ----------------
__global__ void k_prologue(const float* __restrict__ lw, const float* __restrict__ lb,
                           const float* __restrict__ whh, const float* __restrict__ wih,
                           const float* __restrict__ ea) {
    int idx = blockIdx.x * blockDim.x + threadIdx.x;
    int stride = gridDim.x * blockDim.x;

    // zero scatter targets
    float4* aggz = (float4*)g_agg;
    for (int j = idx; j < N_NODES * DIM / 4; j += stride)
        aggz[j] = make_float4(0.f, 0.f, 0.f, 0.f);
    for (int j = idx; j < N_NODES; j += stride) g_cnt[j] = 0.f;

    // pack fp16 B^T for gemm1
    for (int t = idx; t < 1024 * 64; t += stride) {
        int j = t >> 6, i = t & 63;
        float v;
        if (j < 768) {
            v = lw[(size_t)(j >> 6) * 4096 + i * 64 + (j & 63)];
        } else if (j < 832) {
            v = lb[i * 64 + (j - 768)];
        } else {
            v = whh[(j - 832) * 64 + i];
        }
        g_Bh[t] = __float2half_rn(v);
    }
    // pack tf32 w_ih^T for gemm2
    for (int t = idx; t < 64 * 192; t += stride) {
        int i = t / 192, g = t % 192;
        g_B[(size_t)i * BCOLS + 1024 + g] = f2tf32(wih[g * 64 + i]);
    }

    // BN column partial sums
    float s[EDIM], q[EDIM];
#pragma unroll
    for (int c = 0; c < EDIM; c++) { s[c] = 0.f; q[c] = 0.f; }
    for (int e = idx; e < N_EDGES; e += stride) {
        const float* row = ea + (size_t)e * EDIM;
#pragma unroll
        for (int c = 0; c < EDIM; c++) { float v = row[c]; s[c] += v; q[c] += v * v; }
    }
#pragma unroll
    for (int off = 16; off > 0; off >>= 1) {
#pragma unroll
        for (int c = 0; c < EDIM; c++) {
            s[c] += __shfl_down_sync(0xffffffffu, s[c], off);
            q[c] += __shfl_down_sync(0xffffffffu, q[c], off);
        }
    }
    __shared__ float bs[2 * EDIM];
    if (threadIdx.x < 2 * EDIM) bs[threadIdx.x] = 0.f;
    __syncthreads();
    if ((threadIdx.x & 31) == 0) {
#pragma unroll
        for (int c = 0; c < EDIM; c++) {
            atomicAdd(&bs[c], s[c]);
            atomicAdd(&bs[EDIM + c], q[c]);
        }
    }
    __syncthreads();
    if (threadIdx.x < 2 * EDIM)
        g_bnpart[blockIdx.x * 2 * EDIM + threadIdx.x] = bs[threadIdx.x];
}

// ---------------- kernel 2: BN finalize ----------------
__global__ void k_bn_fin(const float* __restrict__ gamma, const float* __restrict__ beta) {
    int t = threadIdx.x;
    __shared__ float red[2 * EDIM];
    if (t < 2 * EDIM) {
        float acc = 0.f;
        for (int b = 0; b < BN_BLOCKS; b++) acc += g_bnpart[b * 2 * EDIM + t];
        red[t] = acc;
    }
    __syncwarp();
    if (t < EDIM) {
        float inv_n = 1.0f / (float)N_EDGES;
        float mu = red[t] * inv_n;
        float var = red[EDIM + t] * inv_n - mu * mu;
        float sc = rsqrtf(var + BN_EPS) * gamma[t];
        g_scale[t] = sc;
        g_shift[t] = beta[t] - mu * sc;
    }
}

// ---------------- fp16 mma helpers ----------------
__device__ __forceinline__ void mma_f16(float* c, const unsigned* a, unsigned b0, unsigned b1) {
    asm volatile(
        "mma.sync.aligned.m16n8k16.row.col.f32.f16.f16.f32 "
        "{%0,%1,%2,%3}, {%4,%5,%6,%7}, {%8,%9}, {%0,%1,%2,%3};"
        : "+f"(c[0]), "+f"(c[1]), "+f"(c[2]), "+f"(c[3])
        : "r"(a[0]), "r"(a[1]), "r"(a[2]), "r"(a[3]), "r"(b0), "r"(b1));
}

__device__ __forceinline__ void ldsm_x4(unsigned* r, unsigned addr) {
    asm volatile("ldmatrix.sync.aligned.m8n8.x4.shared.b16 {%0,%1,%2,%3}, [%4];"
                 : "=r"(r[0]), "=r"(r[1]), "=r"(r[2]), "=r"(r[3]) : "r"(addr));
}

// ---------------- kernel 3: GEMM1 fp16 (exact R8 winner) ----------------
// BM=128, BN=128, K=64. 256 thr, 8 warps (4m x 2n), warp tile 32x64.
// Epilogue staged through smem (pitch 136) for coalesced uint4 stores.
#define EPI_PITCH 136
#define G1_SMEM (128 * EPI_PITCH * 2)   // 34816 B >= tile buffers (32768 B)

__global__ void k_gemm1(const float* __restrict__ x) {
    extern __shared__ char smraw[];
    __half* As = (__half*)smraw;             // [128][64] halves, 16B-chunk swizzle
    __half* Bs = (__half*)smraw + 128 * 64;  // [128 j][64 k] halves, swizzled

    int tid = threadIdx.x;
    int m0 = blockIdx.x * 128;
    int n0 = blockIdx.y * 128;

#pragma unroll
    for (int r = 0; r < 4; r++) {
        int id = r * 256 + tid;
        int m = id >> 3, c = id & 7;
        float4 v0 = make_float4(0.f, 0.f, 0.f, 0.f), v1 = v0;
        if (m0 + m < N_NODES) {
            const float* px = &x[(size_t)(m0 + m) * 64 + c * 8];
            v0 = *(const float4*)px;
            v1 = *(const float4*)(px + 4);
        }
        half2 h[4] = {__floats2half2_rn(v0.x, v0.y), __floats2half2_rn(v0.z, v0.w),
                      __floats2half2_rn(v1.x, v1.y), __floats2half2_rn(v1.z, v1.w)};
        *(uint4*)&As[m * 64 + ((c ^ (m & 7)) << 3)] = *(uint4*)h;
    }
#pragma unroll
    for (int r = 0; r < 4; r++) {
        int id = r * 256 + tid;
        int j = id >> 3, c = id & 7;
        uint4 v = *(const uint4*)&g_Bh[(size_t)(n0 + j) * 64 + c * 8];
        *(uint4*)&Bs[j * 64 + ((c ^ (j & 7)) << 3)] = v;
    }
    __syncthreads();

    int wid = tid >> 5;
    int lane = tid & 31;
    int warp_m = wid & 3;      // 32 rows
    int warp_n = wid >> 2;     // 64 cols
    int lrow = lane & 15;
    int lsel = lane >> 4;

    unsigned a_base = (unsigned)__cvta_generic_to_shared(As);
    unsigned b_base = (unsigned)__cvta_generic_to_shared(Bs);

    float acc[2][8][4];
#pragma unroll
    for (int mt = 0; mt < 2; mt++)
#pragma unroll
        for (int nt = 0; nt < 8; nt++)
#pragma unroll
            for (int j = 0; j < 4; j++) acc[mt][nt][j] = 0.f;

#pragma unroll
    for (int ks = 0; ks < 4; ks++) {
        int chunk = ks * 2 + lsel;
        unsigned a[2][4];
#pragma unroll
        for (int mt = 0; mt < 2; mt++) {
            int row = warp_m * 32 + mt * 16 + lrow;
            ldsm_x4(a[mt], a_base + (row * 64 + ((chunk ^ (row & 7)) << 3)) * 2);
        }
#pragma unroll
        for (int nt2 = 0; nt2 < 4; nt2++) {
            int row = warp_n * 64 + nt2 * 16 + lrow;
            unsigned b[4];
            ldsm_x4(b, b_base + (row * 64 + ((chunk ^ (row & 7)) << 3)) * 2);
            mma_f16(acc[0][nt2 * 2],     a[0], b[0], b[2]);
            mma_f16(acc[0][nt2 * 2 + 1], a[0], b[1], b[3]);
            mma_f16(acc[1][nt2 * 2],     a[1], b[0], b[2]);
            mma_f16(acc[1][nt2 * 2 + 1], a[1], b[1], b[3]);
        }
    }
    __syncthreads();   // done reading tiles; reuse smem for epilogue staging

    __half* Sb = (__half*)smraw;
    int gid = lane >> 2;
    int tig = lane & 3;
#pragma unroll
    for (int mt = 0; mt < 2; mt++) {
#pragma unroll
        for (int nt = 0; nt < 8; nt++) {
            int col = warp_n * 64 + nt * 8 + tig * 2;
            int r0 = warp_m * 32 + mt * 16 + gid;
            *(half2*)&Sb[r0 * EPI_PITCH + col] =
                __floats2half2_rn(acc[mt][nt][0], acc[mt][nt][1]);
            *(half2*)&Sb[(r0 + 8) * EPI_PITCH + col] =
                __floats2half2_rn(acc[mt][nt][2], acc[mt][nt][3]);
        }
    }
    __syncthreads();

#pragma unroll
    for (int r = 0; r < 8; r++) {
        int id = r * 256 + tid;          // 2048 uint4 slots
        int row = id >> 4, c8 = id & 15;
        if (m0 + row < N_NODES) {
            uint4 v = *(uint4*)&Sb[row * EPI_PITCH + c8 * 8];
            *(uint4*)&g_Ph[(size_t)(m0 + row) * PCOLS + n0 + c8 * 8] = v;
        }
    }
}

// ---------------- kernel 4: per-edge message + scatter (2 edges per warp) ----------------
__global__ void k_edge(const float* __restrict__ ea, const int* __restrict__ ei) {
    int wg = (blockIdx.x * blockDim.x + threadIdx.x) >> 5;
    int lane = threadIdx.x & 31;
    int e0 = wg * 2;
    if (e0 >= N_EDGES) return;
    int e1 = e0 + 1;

    int src0 = ei[e0], dst0 = ei[N_EDGES + e0];
    int src1 = ei[e1], dst1 = ei[N_EDGES + e1];

    float eb0 = 0.f, eb1 = 0.f;
    if (lane < EDIM) {
        float sc = g_scale[lane], sh = g_shift[lane];
        eb0 = ea[(size_t)e0 * EDIM + lane] * sc + sh;
        eb1 = ea[(size_t)e1 * EDIM + lane] * sc + sh;
    }

    const half2* p0 = (const half2*)(g_Ph + (size_t)src0 * PCOLS);
    const half2* p1 = (const half2*)(g_Ph + (size_t)src1 * PCOLS);
    float2 acc0 = __half22float2(p0[384 + lane]);   // bias block at col 768
    float2 acc1 = __half22float2(p1[384 + lane]);
#pragma unroll
    for (int k = 0; k < EDIM; k++) {
        float c0 = __shfl_sync(0xffffffffu, eb0, k);
        float c1 = __shfl_sync(0xffffffffu, eb1, k);
        float2 w0 = __half22float2(p0[k * 32 + lane]);
        float2 w1 = __half22float2(p1[k * 32 + lane]);
        acc0.x += c0 * w0.x; acc0.y += c0 * w0.y;
        acc1.x += c1 * w1.x; acc1.y += c1 * w1.y;
    }
    float* a0 = g_agg + (size_t)dst0 * DIM + 2 * lane;
    atomicAdd(a0, acc0.x);
    atomicAdd(a0 + 1, acc0.y);
    float* a1 = g_agg + (size_t)dst1 * DIM + 2 * lane;
    atomicAdd(a1, acc1.x);
    atomicAdd(a1 + 1, acc1.y);
    if (lane == 0) atomicAdd(&g_cnt[dst0], 1.0f);
    if (lane == 1) atomicAdd(&g_cnt[dst1], 1.0f);
}

// ---------------- mma tf32 (gemm2) ----------------
__device__ __forceinline__ void mma_tf32(float* c, const unsigned* a, unsigned b0, unsigned b1) {
    asm volatile(
        "mma.sync.aligned.m16n8k8.row.col.f32.tf32.tf32.f32 "
        "{%0,%1,%2,%3}, {%4,%5,%6,%7}, {%8,%9}, {%0,%1,%2,%3};"
        : "+f"(c[0]), "+f"(c[1]), "+f"(c[2]), "+f"(c[3])
        : "r"(a[0]), "r"(a[1]), "r"(a[2]), "r"(a[3]), "r"(b0), "r"(b1));
}

#define GA_PITCH 68
#define GB_PITCH 132
#define G2_SMEM ((128 * GA_PITCH + 64 * GB_PITCH) * 4)

// ---------------- kernel 5: GEMM2  GI = relu(agg)/cnt @ B[:, 1024:1216] ----------------
__global__ void k_gemm2() {
    extern __shared__ char smraw[];
    float* As = (float*)smraw;
    float* Bs = (float*)smraw + 128 * GA_PITCH;
    const float* Bg = g_B + 1024;
    const int Ncols = 192;

    int tid = threadIdx.x;
    int m0 = blockIdx.x * 128;
    int n0 = blockIdx.y * 128;

#pragma unroll
    for (int r = 0; r < 8; r++) {
        int id = r * 256 + tid;
        int m = id >> 4;
        int k4 = (id & 15) << 2;
        float4 v = make_float4(0.f, 0.f, 0.f, 0.f);
        int node = m0 + m;
        if (node < N_NODES) {
            float inv = 1.0f / fmaxf(g_cnt[node], 1.0f);
            float4 a = *(const float4*)&g_agg[(size_t)node * 64 + k4];
            v.x = fmaxf(a.x, 0.f) * inv;
            v.y = fmaxf(a.y, 0.f) * inv;
            v.z = fmaxf(a.z, 0.f) * inv;
            v.w = fmaxf(a.w, 0.f) * inv;
        }
        v.x = f2tf32(v.x); v.y = f2tf32(v.y); v.z = f2tf32(v.z); v.w = f2tf32(v.w);
        *(float4*)&As[m * GA_PITCH + k4] = v;
    }
#pragma unroll
    for (int r = 0; r < 8; r++) {
        int id = r * 256 + tid;
        int k = id >> 5;
        int n4 = (id & 31) << 2;
        float4 v = make_float4(0.f, 0.f, 0.f, 0.f);
        if (n0 + n4 < Ncols) v = *(const float4*)&Bg[(size_t)k * BCOLS + n0 + n4];
        *(float4*)&Bs[k * GB_PITCH + n4] = v;
    }
    __syncthreads();

    int wid = tid >> 5;
    int lane = tid & 31;
    int gid = lane >> 2;
    int tig = lane & 3;
    int warp_m = wid & 3;
    int warp_n = wid >> 2;

    float acc[2][8][4];
#pragma unroll
    for (int mt = 0; mt < 2; mt++)
#pragma unroll
        for (int nt = 0; nt < 8; nt++)
#pragma unroll
            for (int j = 0; j < 4; j++) acc[mt][nt][j] = 0.f;

#pragma unroll
    for (int ks = 0; ks < 8; ks++) {
        int k0 = ks * 8;
        unsigned a[2][4];
#pragma unroll
        for (int mt = 0; mt < 2; mt++) {
            int rowb = warp_m * 32 + mt * 16;
            a[mt][0] = __float_as_uint(As[(rowb + gid) * GA_PITCH + k0 + tig]);
            a[mt][1] = __float_as_uint(As[(rowb + gid + 8) * GA_PITCH + k0 + tig]);
            a[mt][2] = __float_as_uint(As[(rowb + gid) * GA_PITCH + k0 + tig + 4]);
            a[mt][3] = __float_as_uint(As[(rowb + gid + 8) * GA_PITCH + k0 + tig + 4]);
        }
#pragma unroll
        for (int nt = 0; nt < 8; nt++) {
            int nb = warp_n * 64 + nt * 8 + gid;
            unsigned b0 = __float_as_uint(Bs[(k0 + tig) * GB_PITCH + nb]);
            unsigned b1 = __float_as_uint(Bs[(k0 + tig + 4) * GB_PITCH + nb]);
            mma_tf32(acc[0][nt], a[0], b0, b1);
            mma_tf32(acc[1][nt], a[1], b0, b1);
        }
    }

#pragma unroll
    for (int mt = 0; mt < 2; mt++) {
#pragma unroll
        for (int nt = 0; nt < 8; nt++) {
            int col = n0 + warp_n * 64 + nt * 8 + tig * 2;
            if (col >= Ncols) continue;
            int r0 = m0 + warp_m * 32 + mt * 16 + gid;
            if (r0 < N_NODES)
                *(float2*)&g_GI[(size_t)r0 * 192 + col] = make_float2(acc[mt][nt][0], acc[mt][nt][1]);
            int r1 = r0 + 8;
            if (r1 < N_NODES)
                *(float2*)&g_GI[(size_t)r1 * 192 + col] = make_float2(acc[mt][nt][2], acc[mt][nt][3]);
        }
    }
}

// ---------------- kernel 6: elementwise GRU ----------------
__global__ void k_out(const float* __restrict__ x,
                      const float* __restrict__ bih, const float* __restrict__ bhh,
                      float* __restrict__ out) {
    int idx = blockIdx.x * blockDim.x + threadIdx.x;
    if (idx >= N_NODES * DIM) return;
    int n = idx >> 6;
    int o = idx & 63;

    const float* gi = g_GI + (size_t)n * 192;
    const __half* gh = g_Ph + (size_t)n * PCOLS + 832;

    float ir = gi[o] + bih[o];
    float iz = gi[64 + o] + bih[64 + o];
    float in_ = gi[128 + o] + bih[128 + o];
    float hr = __half2float(gh[o]) + bhh[o];
    float hz = __half2float(gh[64 + o]) + bhh[64 + o];
    float hn = __half2float(gh[128 + o]) + bhh[128 + o];

    float r = 1.0f / (1.0f + __expf(-(ir + hr)));
    float z = 1.0f / (1.0f + __expf(-(iz + hz)));
    float nn = tanhf(in_ + r * hn);
    float xv = x[idx];
    out[idx] = (1.0f - z) * nn + z * xv;
}

// ---------------- host ----------------
extern "C" void kernel_launch(void* const* d_in, const int* in_sizes, int n_in,
                              void* d_out, int out_size) {
    const float* x     = (const float*)d_in[0];
    const int*   ei    = (const int*)d_in[1];
    const float* ea    = (const float*)d_in[2];
    const float* gamma = (const float*)d_in[3];
    const float* beta  = (const float*)d_in[4];
    const float* lw    = (const float*)d_in[5];
    const float* lb    = (const float*)d_in[6];
    const float* wih   = (const float*)d_in[7];
    const float* whh   = (const float*)d_in[8];
    const float* bih   = (const float*)d_in[9];
    const float* bhh   = (const float*)d_in[10];
    float* out = (float*)d_out;

    cudaFuncSetAttribute(k_gemm2, cudaFuncAttributeMaxDynamicSharedMemorySize, G2_SMEM);

    k_prologue<<<BN_BLOCKS, 256>>>(lw, lb, whh, wih, ea);
    k_bn_fin<<<1, 32>>>(gamma, beta);

    dim3 g1((N_NODES + 127) / 128, PCOLS / 128);
    k_gemm1<<<g1, 256, G1_SMEM>>>(x);

    // 2 edges per warp: 40000 warps -> 5000 blocks of 8 warps
    k_edge<<<(N_EDGES / 2 * 32) / 256, 256>>>(ea, ei);

    dim3 g2((N_NODES + 127) / 128, 2);
    k_gemm2<<<g2, 256, G2_SMEM>>>();

    k_out<<<(N_NODES * DIM + 255) / 256, 256>>>(x, bih, bhh, out);
}